// round 13
// baseline (speedup 1.0000x reference)
#include <cuda_runtime.h>
#include <cstdint>

// ESN recurrence, persistent kernel, v5: R8 base + split two-level barrier.
// T=1000, B=64, I=80, H=1024, LEAK=0.5.
// Grid: 128 CTAs = 64 j-groups (16 cols) x 2 b-groups (32 batch).
// 16 warps split K (64 k each); lane tile 4 j x 2 batch-pairs, f32x2 packed.
// Per-step sync: per-bg (64 CTA) two-level tree barrier (8 groups of 8).

#define BB    64
#define II    80
#define HH    1024
#define NCTA  128
#define JC    16
#define BPC   16
#define NBG   2
#define NTHR  512
#define NWARP 16
#define KPW   (HH / NWARP)   // 64
#define IPW   (II / NWARP)   // 5
#define T_MAX 1024

typedef unsigned long long u64;

__device__ __align__(16) u64 g_h[2][NBG][HH][BPC];
__device__ __align__(16) float g_xT[T_MAX * II * BB];   // [t][i][b]

// one-time full-grid barrier state
__device__ unsigned g_bar_count = 0;
__device__ volatile unsigned g_bar_gen = 0;
// per-step split barrier state (each counter on its own 128B line)
__device__ unsigned g_sub[NBG][8][32];
__device__ unsigned g_top[NBG][32];
__device__ volatile unsigned g_gen[NBG][32];

__device__ __forceinline__ u64 ffma2(u64 a, u64 b, u64 c) {
    u64 d; asm("fma.rn.f32x2 %0, %1, %2, %3;" : "=l"(d) : "l"(a), "l"(b), "l"(c)); return d;
}
__device__ __forceinline__ u64 fadd2(u64 a, u64 b) {
    u64 d; asm("add.rn.f32x2 %0, %1, %2;" : "=l"(d) : "l"(a), "l"(b)); return d;
}
__device__ __forceinline__ u64 pack2(float lo, float hi) {
    u64 d; asm("mov.b64 %0, {%1, %2};" : "=l"(d) : "f"(lo), "f"(hi)); return d;
}
__device__ __forceinline__ float lo2(u64 v) { return __uint_as_float((unsigned)v); }
__device__ __forceinline__ float hi2(u64 v) { return __uint_as_float((unsigned)(v >> 32)); }

// one-time global barrier (init only)
__device__ __forceinline__ void grid_barrier_all() {
    __syncthreads();
    if (threadIdx.x == 0) {
        __threadfence();
        unsigned g = g_bar_gen;
        if (atomicAdd(&g_bar_count, 1u) == gridDim.x - 1u) {
            g_bar_count = 0;
            __threadfence();
            g_bar_gen = g + 1u;
        } else {
            while (g_bar_gen == g) { }
        }
        __threadfence();
    }
    __syncthreads();
}

// per-step barrier over the 64 CTAs of one bg: 8 sub-groups of 8 -> top of 8
__device__ __forceinline__ void bg_barrier(int bg, int grp) {
    __syncthreads();
    if (threadIdx.x == 0) {
        __threadfence();                         // publish h/out stores
        unsigned g = g_gen[bg][0];               // read BEFORE arriving
        if (atomicAdd(&g_sub[bg][grp][0], 1u) == 7u) {
            g_sub[bg][grp][0] = 0u;
            __threadfence();                     // order reset before top arrive
            if (atomicAdd(&g_top[bg][0], 1u) == 7u) {
                g_top[bg][0] = 0u;
                __threadfence();
                g_gen[bg][0] = g + 1u;
            }
        }
        while (g_gen[bg][0] == g) { }
        __threadfence();                         // acquire
    }
    __syncthreads();
}

// dynamic SMEM:
//  [0,131072)        Ws   : W_hh slice [k][16 j] dup f32x2 (u64)
//  [131072,141312)   Wihs : W_ih slice [i][16 j] dup f32x2 (u64)
//  [141312,174080)   red  : [16 w][16 j][16 bp] u64       (union xs)
//  [174080,176128)   outs : [16 j][32 b] float
//  [141312,162048)   xs   : [64][81] float transpose scratch (staging only)
#define WS_OFF   0
#define WIH_OFF  131072
#define RED_OFF  141312
#define OUT_OFF  174080
#define XS_OFF   141312
#define SMEM_BYTES 176128

extern "C" __global__ void __launch_bounds__(NTHR, 1)
esn_kernel(const float* __restrict__ x, const int* __restrict__ lengths,
           const float* __restrict__ W_ih, const float* __restrict__ W_hh,
           float* __restrict__ out, int T)
{
    extern __shared__ unsigned char smem[];
    u64*   Ws   = (u64*)(smem + WS_OFF);
    u64*   Wihs = (u64*)(smem + WIH_OFF);
    u64*   red  = (u64*)(smem + RED_OFF);
    float* outs = (float*)(smem + OUT_OFF);
    float* xs   = (float*)(smem + XS_OFF);

    const int tid = threadIdx.x;
    const int w   = tid >> 5;
    const int l   = tid & 31;
    const int jf  = l >> 3;      // 0..3 -> j local {4jf..4jf+3}
    const int bq  = l & 7;       // 0..7 -> bp local {2bq,2bq+1}
    const int bx  = blockIdx.x;
    const int jg  = bx >> 1, bg = bx & 1;
    const int grp = jg >> 3;     // 8 CTAs per sub-group
    const int j0  = jg * JC;
    const int b0  = bg * 32;

    // ---- one-time staging ----
    for (int idx = tid; idx < JC * HH; idx += NTHR) {
        int j = idx >> 10, k = idx & 1023;            // coalesced over k
        float v = W_hh[(size_t)(j0 + j) * HH + k];
        Ws[k * JC + j] = pack2(v, v);
    }
    for (int idx = tid; idx < II * JC; idx += NTHR) {
        int i = idx >> 4, j = idx & 15;
        float v = W_ih[(j0 + j) * II + i];
        Wihs[i * JC + j] = pack2(v, v);
    }
    if (tid < JC * BPC)
        g_h[0][bg][j0 + (tid >> 4)][tid & 15] = 0ull;

    // transpose x[t][b][i] -> g_xT[t][i][b]
    for (int tt = blockIdx.x; tt < T; tt += NCTA) {
        __syncthreads();
        const float4* src = (const float4*)(x + (size_t)tt * BB * II);
        for (int idx = tid; idx < (BB * II) / 4; idx += NTHR) {
            float4 v = src[idx];
            int base = idx * 4;
            int b = base / II, i = base % II;
            float* dst = &xs[b * 81 + i];
            dst[0] = v.x; dst[1] = v.y; dst[2] = v.z; dst[3] = v.w;
        }
        __syncthreads();
        for (int idx = tid; idx < BB * II; idx += NTHR) {
            int i = idx >> 6, b = idx & 63;
            g_xT[((size_t)tt * II + i) * BB + b] = xs[b * 81 + i];
        }
    }

    // finalize role (first 256 threads): thread = (fj, fb)
    const int fj = (tid >> 4) & 15;
    const int fb = tid & 15;
    const int gb = b0 + 2 * fb;
    const int len0 = __ldg(lengths + gb);
    const int len1 = __ldg(lengths + gb + 1);

    grid_barrier_all();               // weights, h0, xT visible everywhere

    const int kb = w * KPW;

    for (int t = 0; t < T; ++t) {
        const int rb = t & 1, wb = rb ^ 1;

        // ---- fill h prefetch ring (8 deep) ----
        const u64* hp = &g_h[rb][bg][0][0] + (size_t)kb * BPC + 2 * bq;
        ulonglong2 ring[8];
        #pragma unroll
        for (int d = 0; d < 8; ++d)
            ring[d] = __ldcg((const ulonglong2*)(hp + d * BPC));

        u64 acc[4][2];
        #pragma unroll
        for (int jj = 0; jj < 4; ++jj) { acc[jj][0] = 0ull; acc[jj][1] = 0ull; }

        // ---- input drive over my i-range (covers ring-fill latency) ----
        {
            const float* xbase = g_xT + ((size_t)t * II + w * IPW) * BB + b0 + 4 * bq;
            const ulonglong2* wih = (const ulonglong2*)(Wihs + (size_t)(w * IPW) * JC) + 2 * jf;
            #pragma unroll
            for (int u = 0; u < IPW; ++u) {
                ulonglong2 x2 = *(const ulonglong2*)(xbase + u * BB);
                ulonglong2 wa = wih[u * 8];
                ulonglong2 wc = wih[u * 8 + 1];
                acc[0][0] = ffma2(x2.x, wa.x, acc[0][0]); acc[0][1] = ffma2(x2.y, wa.x, acc[0][1]);
                acc[1][0] = ffma2(x2.x, wa.y, acc[1][0]); acc[1][1] = ffma2(x2.y, wa.y, acc[1][1]);
                acc[2][0] = ffma2(x2.x, wc.x, acc[2][0]); acc[2][1] = ffma2(x2.y, wc.x, acc[2][1]);
                acc[3][0] = ffma2(x2.x, wc.y, acc[3][0]); acc[3][1] = ffma2(x2.y, wc.y, acc[3][1]);
            }
        }

        // ---- recurrent part: 8 FFMA2 per 3 L1 ops per k ----
        {
            const ulonglong2* wsp = (const ulonglong2*)(Ws + (size_t)kb * JC) + 2 * jf;
            #pragma unroll 8
            for (int kt = 0; kt < KPW; ++kt) {
                ulonglong2 h2 = ring[kt & 7];
                if (kt + 8 < KPW)
                    ring[kt & 7] = __ldcg((const ulonglong2*)(hp + (kt + 8) * BPC));
                ulonglong2 wa = wsp[kt * 8];
                ulonglong2 wc = wsp[kt * 8 + 1];
                acc[0][0] = ffma2(h2.x, wa.x, acc[0][0]); acc[0][1] = ffma2(h2.y, wa.x, acc[0][1]);
                acc[1][0] = ffma2(h2.x, wa.y, acc[1][0]); acc[1][1] = ffma2(h2.y, wa.y, acc[1][1]);
                acc[2][0] = ffma2(h2.x, wc.x, acc[2][0]); acc[2][1] = ffma2(h2.y, wc.x, acc[2][1]);
                acc[3][0] = ffma2(h2.x, wc.y, acc[3][0]); acc[3][1] = ffma2(h2.y, wc.y, acc[3][1]);
            }
        }

        // prefetch old h for finalize slot (hides L2 latency behind sync)
        u64 hold = 0ull;
        if (tid < 256) hold = __ldcg(&g_h[rb][bg][j0 + fj][fb]);

        // ---- write partials ----
        #pragma unroll
        for (int jj = 0; jj < 4; ++jj) {
            *(ulonglong2*)(red + ((size_t)(w * JC + 4 * jf + jj) * BPC + 2 * bq)) =
                make_ulonglong2(acc[jj][0], acc[jj][1]);
        }
        __syncthreads();

        // ---- finalize (256 threads): 16-way reduce (4 chains) + tanh ----
        if (tid < 256) {
            const u64* rp = red + (size_t)fj * BPC + fb;
            u64 s0 = rp[0 * 256], s1 = rp[1 * 256], s2 = rp[2 * 256], s3 = rp[3 * 256];
            #pragma unroll
            for (int p = 4; p < NWARP; p += 4) {
                s0 = fadd2(s0, rp[(p + 0) * 256]);
                s1 = fadd2(s1, rp[(p + 1) * 256]);
                s2 = fadd2(s2, rp[(p + 2) * 256]);
                s3 = fadd2(s3, rp[(p + 3) * 256]);
            }
            u64 s = fadd2(fadd2(s0, s1), fadd2(s2, s3));

            float h0v = lo2(hold), h1v = hi2(hold);
            float nh0 = h0v, nh1 = h1v;
            bool v0 = t < len0, v1 = t < len1;
            if (v0) nh0 = 0.5f * h0v + 0.5f * tanhf(lo2(s));
            if (v1) nh1 = 0.5f * h1v + 0.5f * tanhf(hi2(s));
            g_h[wb][bg][j0 + fj][fb] = pack2(nh0, nh1);

            outs[fj * 32 + 2 * fb]     = v0 ? nh0 : 0.0f;
            outs[fj * 32 + 2 * fb + 1] = v1 ? nh1 : 0.0f;
        }
        __syncthreads();

        // ---- coalesced output store: 512 elems, 1 per thread ----
        {
            float* ob = out + ((size_t)t * BB + b0) * HH + j0;
            int bl = tid >> 4, jj = tid & 15;
            ob[(size_t)bl * HH + jj] = outs[jj * 32 + bl];
        }

        bg_barrier(bg, grp);          // only my 64-CTA batch group
    }
}

extern "C" void kernel_launch(void* const* d_in, const int* in_sizes, int n_in,
                              void* d_out, int out_size) {
    const float* x       = (const float*)d_in[0];
    const int*   lengths = (const int*)d_in[1];
    const float* W_ih    = (const float*)d_in[2];
    const float* W_hh    = (const float*)d_in[3];
    float*       out     = (float*)d_out;
    int T = in_sizes[0] / (BB * II);

    cudaFuncSetAttribute(esn_kernel, cudaFuncAttributeMaxDynamicSharedMemorySize, SMEM_BYTES);
    esn_kernel<<<NCTA, NTHR, SMEM_BYTES>>>(x, lengths, W_ih, W_hh, out, T);
}

// round 15
// speedup vs baseline: 1.3240x; 1.3240x over previous
#include <cuda_runtime.h>
#include <cstdint>

// ESN recurrence, persistent kernel, v6: scalar weights + j-vector f32x2.
// T=1000, B=64, I=80, H=1024, LEAK=0.5.
// Grid: 128 CTAs = 64 j-groups (16 cols) x 2 b-groups (32 batch).
// 16 warps split K (64 k each). Lane = (jf 0..3, bq 0..7):
//   per k: LDS.128 -> 4 scalar weights (2 natural f32x2 j-pairs),
//          LDG.128 -> h[k][4bq..4bq+3] (4 batches), 4 reg-dups, 8 FFMA2.
// Halves weight smem wavefronts vs duplicated-weight layout.

#define BB    64
#define II    80
#define HH    1024
#define NCTA  128
#define JC    16
#define NB    32          // batches per CTA
#define NBG   2
#define NTHR  512
#define NWARP 16
#define KPW   (HH / NWARP)   // 64
#define IPW   (II / NWARP)   // 5
#define T_MAX 1024

typedef unsigned long long u64;

__device__ __align__(16) float g_h[2][NBG][HH][NB];     // scalar h, [k][b]
__device__ __align__(16) float g_xT[T_MAX * II * BB];   // [t][i][b]
__device__ unsigned g_bar_count = 0;
__device__ volatile unsigned g_bar_gen = 0;

__device__ __forceinline__ u64 ffma2(u64 a, u64 b, u64 c) {
    u64 d; asm("fma.rn.f32x2 %0, %1, %2, %3;" : "=l"(d) : "l"(a), "l"(b), "l"(c)); return d;
}
__device__ __forceinline__ u64 fadd2(u64 a, u64 b) {
    u64 d; asm("add.rn.f32x2 %0, %1, %2;" : "=l"(d) : "l"(a), "l"(b)); return d;
}
__device__ __forceinline__ u64 dup2(float v) {
    u64 d; asm("mov.b64 %0, {%1, %1};" : "=l"(d) : "f"(v)); return d;
}
__device__ __forceinline__ float lo2(u64 v) { return __uint_as_float((unsigned)v); }
__device__ __forceinline__ float hi2(u64 v) { return __uint_as_float((unsigned)(v >> 32)); }

__device__ __forceinline__ void grid_barrier() {
    __syncthreads();
    if (threadIdx.x == 0) {
        __threadfence();
        unsigned g = g_bar_gen;                  // read BEFORE arriving
        if (atomicAdd(&g_bar_count, 1u) == gridDim.x - 1u) {
            g_bar_count = 0;
            __threadfence();
            g_bar_gen = g + 1u;
        } else {
            while (g_bar_gen == g) { }
        }
        __threadfence();
    }
    __syncthreads();
}

// dynamic SMEM:
//  [0,65536)         Ws   : W_hh slice [k][16 j] scalar f32
//  [65536,70656)     Wihs : W_ih slice [i][16 j] scalar f32
//  [70656,103424)    red  : [16 w][8 jp][32 b] u64 (f32x2 over j-pair)  (union xs)
//  [103424,105536)   outs : [16 j][33] float (padded rows)
//  [70656,91392)     xs   : [64][81] float transpose scratch (staging only)
#define WS_OFF   0
#define WIH_OFF  65536
#define RED_OFF  70656
#define OUT_OFF  103424
#define XS_OFF   70656
#define SMEM_BYTES 105536

extern "C" __global__ void __launch_bounds__(NTHR, 1)
esn_kernel(const float* __restrict__ x, const int* __restrict__ lengths,
           const float* __restrict__ W_ih, const float* __restrict__ W_hh,
           float* __restrict__ out, int T)
{
    extern __shared__ unsigned char smem[];
    float* Ws   = (float*)(smem + WS_OFF);
    float* Wihs = (float*)(smem + WIH_OFF);
    u64*   red  = (u64*)(smem + RED_OFF);
    float* outs = (float*)(smem + OUT_OFF);
    float* xs   = (float*)(smem + XS_OFF);

    const int tid = threadIdx.x;
    const int w   = tid >> 5;
    const int l   = tid & 31;
    const int jf  = l >> 3;      // 0..3 -> j-pairs {2jf, 2jf+1} -> j {4jf..4jf+3}
    const int bq  = l & 7;       // 0..7 -> batches {4bq..4bq+3}
    const int bx  = blockIdx.x;
    const int jg  = bx >> 1, bg = bx & 1;
    const int j0  = jg * JC;
    const int b0  = bg * NB;

    // ---- one-time staging ----
    for (int idx = tid; idx < JC * HH; idx += NTHR) {
        int j = idx >> 10, k = idx & 1023;            // coalesced over k
        Ws[k * JC + j] = W_hh[(size_t)(j0 + j) * HH + k];
    }
    for (int idx = tid; idx < II * JC; idx += NTHR) {
        int i = idx >> 4, j = idx & 15;
        Wihs[i * JC + j] = W_ih[(j0 + j) * II + i];
    }
    // zero my h[0] slice: rows j0..j0+15, 32 b
    if (tid < JC * NB)
        g_h[0][bg][j0 + (tid >> 5)][tid & 31] = 0.0f;

    // transpose x[t][b][i] -> g_xT[t][i][b]
    for (int tt = blockIdx.x; tt < T; tt += NCTA) {
        __syncthreads();
        const float4* src = (const float4*)(x + (size_t)tt * BB * II);
        for (int idx = tid; idx < (BB * II) / 4; idx += NTHR) {
            float4 v = src[idx];
            int base = idx * 4;
            int b = base / II, i = base % II;
            float* dst = &xs[b * 81 + i];
            dst[0] = v.x; dst[1] = v.y; dst[2] = v.z; dst[3] = v.w;
        }
        __syncthreads();
        for (int idx = tid; idx < BB * II; idx += NTHR) {
            int i = idx >> 6, b = idx & 63;
            g_xT[((size_t)tt * II + i) * BB + b] = xs[b * 81 + i];
        }
    }

    // finalize role (first 256 threads): thread = (jpf 0..7, bf 0..31)
    const int jpf = (tid >> 5) & 7;
    const int bf  = tid & 31;
    const int lenf = __ldg(lengths + b0 + bf);

    grid_barrier();                   // weights, h0, xT visible

    const int kb = w * KPW;

    for (int t = 0; t < T; ++t) {
        const int rb = t & 1, wb = rb ^ 1;

        // ---- fill h prefetch ring (8 deep): float4 = 4 batches ----
        const float4* hp4 = (const float4*)&g_h[rb][bg][0][0] + (size_t)kb * (NB / 4) + bq;
        float4 ring[8];
        #pragma unroll
        for (int d = 0; d < 8; ++d)
            ring[d] = __ldcg(hp4 + d * (NB / 4));

        u64 acc[2][4];
        #pragma unroll
        for (int jp = 0; jp < 2; ++jp)
            #pragma unroll
            for (int b = 0; b < 4; ++b) acc[jp][b] = 0ull;

        // ---- input drive over my i-range (covers ring-fill latency) ----
        {
            const float4* xb = (const float4*)(g_xT + ((size_t)t * II + w * IPW) * BB + b0) + bq;
            const ulonglong2* wih = (const ulonglong2*)Wihs + (size_t)(w * IPW) * 4 + jf;
            #pragma unroll
            for (int u = 0; u < IPW; ++u) {
                float4 x4 = __ldg(xb + u * (BB / 4));
                ulonglong2 w2 = wih[u * 4];
                u64 d0 = dup2(x4.x), d1 = dup2(x4.y), d2 = dup2(x4.z), d3 = dup2(x4.w);
                acc[0][0] = ffma2(w2.x, d0, acc[0][0]); acc[0][1] = ffma2(w2.x, d1, acc[0][1]);
                acc[0][2] = ffma2(w2.x, d2, acc[0][2]); acc[0][3] = ffma2(w2.x, d3, acc[0][3]);
                acc[1][0] = ffma2(w2.y, d0, acc[1][0]); acc[1][1] = ffma2(w2.y, d1, acc[1][1]);
                acc[1][2] = ffma2(w2.y, d2, acc[1][2]); acc[1][3] = ffma2(w2.y, d3, acc[1][3]);
            }
        }

        // ---- recurrent part: 1 LDS.128 + 1 LDG.128 + 8 FFMA2 per k ----
        {
            const ulonglong2* wsp = (const ulonglong2*)Ws + (size_t)kb * 4 + jf;
            #pragma unroll 8
            for (int kt = 0; kt < KPW; ++kt) {
                float4 h4 = ring[kt & 7];
                if (kt + 8 < KPW)
                    ring[kt & 7] = __ldcg(hp4 + (kt + 8) * (NB / 4));
                ulonglong2 w2 = wsp[kt * 4];
                u64 d0 = dup2(h4.x), d1 = dup2(h4.y), d2 = dup2(h4.z), d3 = dup2(h4.w);
                acc[0][0] = ffma2(w2.x, d0, acc[0][0]); acc[0][1] = ffma2(w2.x, d1, acc[0][1]);
                acc[0][2] = ffma2(w2.x, d2, acc[0][2]); acc[0][3] = ffma2(w2.x, d3, acc[0][3]);
                acc[1][0] = ffma2(w2.y, d0, acc[1][0]); acc[1][1] = ffma2(w2.y, d1, acc[1][1]);
                acc[1][2] = ffma2(w2.y, d2, acc[1][2]); acc[1][3] = ffma2(w2.y, d3, acc[1][3]);
            }
        }

        // prefetch old h for finalize slot (hides L2 latency behind sync)
        float hold0 = 0.0f, hold1 = 0.0f;
        if (tid < 256) {
            hold0 = __ldcg(&g_h[rb][bg][j0 + 2 * jpf][bf]);
            hold1 = __ldcg(&g_h[rb][bg][j0 + 2 * jpf + 1][bf]);
        }

        // ---- write partials: red[w][jp][b], value = f32x2 over (2jp, 2jp+1) ----
        {
            u64* rp = red + ((size_t)(w * 8 + 2 * jf) * NB + 4 * bq);
            ((ulonglong2*)rp)[0] = make_ulonglong2(acc[0][0], acc[0][1]);
            ((ulonglong2*)rp)[1] = make_ulonglong2(acc[0][2], acc[0][3]);
            rp += NB;
            ((ulonglong2*)rp)[0] = make_ulonglong2(acc[1][0], acc[1][1]);
            ((ulonglong2*)rp)[1] = make_ulonglong2(acc[1][2], acc[1][3]);
        }
        __syncthreads();

        // ---- finalize (256 threads): 16-way reduce (4 chains) + tanh ----
        if (tid < 256) {
            const u64* q = red + (size_t)jpf * NB + bf;
            u64 s0 = q[0], s1 = q[256], s2 = q[512], s3 = q[768];
            #pragma unroll
            for (int p = 4; p < NWARP; p += 4) {
                s0 = fadd2(s0, q[(p + 0) * 256]);
                s1 = fadd2(s1, q[(p + 1) * 256]);
                s2 = fadd2(s2, q[(p + 2) * 256]);
                s3 = fadd2(s3, q[(p + 3) * 256]);
            }
            u64 s = fadd2(fadd2(s0, s1), fadd2(s2, s3));

            bool v = t < lenf;
            float nh0 = hold0, nh1 = hold1;
            if (v) {
                nh0 = 0.5f * hold0 + 0.5f * tanhf(lo2(s));
                nh1 = 0.5f * hold1 + 0.5f * tanhf(hi2(s));
            }
            g_h[wb][bg][j0 + 2 * jpf][bf]     = nh0;
            g_h[wb][bg][j0 + 2 * jpf + 1][bf] = nh1;

            outs[(2 * jpf) * 33 + bf]     = v ? nh0 : 0.0f;
            outs[(2 * jpf + 1) * 33 + bf] = v ? nh1 : 0.0f;
        }
        __syncthreads();

        // ---- coalesced output store: out[t][b0+bl][j0+jj], 512 elems ----
        {
            float* ob = out + ((size_t)t * BB + b0) * HH + j0;
            int bl = tid >> 4, jj = tid & 15;
            ob[(size_t)bl * HH + jj] = outs[jj * 33 + bl];
        }

        grid_barrier();
    }
}

extern "C" void kernel_launch(void* const* d_in, const int* in_sizes, int n_in,
                              void* d_out, int out_size) {
    const float* x       = (const float*)d_in[0];
    const int*   lengths = (const int*)d_in[1];
    const float* W_ih    = (const float*)d_in[2];
    const float* W_hh    = (const float*)d_in[3];
    float*       out     = (float*)d_out;
    int T = in_sizes[0] / (BB * II);

    cudaFuncSetAttribute(esn_kernel, cudaFuncAttributeMaxDynamicSharedMemorySize, SMEM_BYTES);
    esn_kernel<<<NCTA, NTHR, SMEM_BYTES>>>(x, lengths, W_ih, W_hh, out, T);
}